// round 16
// baseline (speedup 1.0000x reference)
#include <cuda_runtime.h>
#include <cuda_bf16.h>
#include <math.h>
#include <stdint.h>

namespace fa {

constexpr int N4 = 4096, D = 64, J = 256, BH = 32, SPLIT = 16;
constexpr size_t NT = (size_t)BH * N4;          // 131072 rows

constexpr float DATA_NORM = 0.35355339059327373f;
constexpr float RATIO     = 0.0625f;
constexpr float DIAG_C    = 0.0625f;
constexpr float KEPS      = 1e-4f;

// ---- scratch ----
// P in mma-B fragment order: [jtile(32)][ks(4)][lane(32)][4: hi0,hi1,lo0,lo1]
__device__ __align__(16) uint32_t g_Pf[32 * 4 * 32 * 4];
__device__ float    g_vsump[BH * SPLIT * 64];
__device__ float    g_ctxp[(size_t)BH * SPLIT * 256 * 72];
// [ctx^T|ksum] in B-fragment order: [bh][nt(9)][kc(16)][lane(32)][4]
__device__ __align__(16) uint32_t g_boutf[BH * 18432];
__device__ unsigned g_kmax_u;

__device__ __forceinline__ unsigned fenc(float f) {
    unsigned u = __float_as_uint(f);
    return (u & 0x80000000u) ? ~u : (u | 0x80000000u);
}
__device__ __forceinline__ float fdec(unsigned u) {
    unsigned b = (u & 0x80000000u) ? (u & 0x7fffffffu) : ~u;
    return __uint_as_float(b);
}
__device__ __forceinline__ uint32_t bpack(float a, float b) {
    uint32_t r;
    asm("cvt.rn.bf16x2.f32 %0, %1, %2;" : "=r"(r) : "f"(b), "f"(a));
    return r;
}
__device__ __forceinline__ void split2(float a, float b, uint32_t& hi, uint32_t& lo) {
    hi = bpack(a, b);
    float ha = __uint_as_float(hi << 16);
    float hb = __uint_as_float(hi & 0xffff0000u);
    lo = bpack(a - ha, b - hb);
}
// fp32 exp via FMA-pipe poly (rel err ~1.7e-7)
__device__ __forceinline__ float fexp(float x) {
    float t = x * 1.4426950408889634f;
    float r = rintf(t);
    float f = t - r;
    float p = 1.53989857e-4f;
    p = fmaf(p, f, 1.33335581e-3f);
    p = fmaf(p, f, 9.61812910e-3f);
    p = fmaf(p, f, 5.55041087e-2f);
    p = fmaf(p, f, 2.40226507e-1f);
    p = fmaf(p, f, 6.93147181e-1f);
    p = fmaf(p, f, 1.0f);
    int ei = (int)r;
    ei = ei < -126 ? -126 : (ei > 127 ? 127 : ei);
    return p * __int_as_float((ei + 127) << 23);
}
__device__ __forceinline__ void mma16(float* c, const uint32_t* a, const uint32_t* b) {
    asm volatile(
        "mma.sync.aligned.m16n8k16.row.col.f32.bf16.bf16.f32 "
        "{%0,%1,%2,%3}, {%4,%5,%6,%7}, {%8,%9}, {%0,%1,%2,%3};"
        : "+f"(c[0]), "+f"(c[1]), "+f"(c[2]), "+f"(c[3])
        : "r"(a[0]), "r"(a[1]), "r"(a[2]), "r"(a[3]), "r"(b[0]), "r"(b[1]));
}

// ===========================================================================
// Prep P -> g_Pf (B-fragment order) + init max.  <<<1,256>>>, thread = row j.
// ===========================================================================
__global__ void k_prep_P(const float* __restrict__ P)
{
    const int j = threadIdx.x;
    if (j == 0) g_kmax_u = 0x007FFFFFu;
    const int ntg = j >> 3, qr = j & 7;
#pragma unroll
    for (int c = 0; c < 32; c++) {
        uint32_t hi, lo;
        split2(P[j * 64 + 2 * c], P[j * 64 + 2 * c + 1], hi, lo);
        int ks = c >> 3, cc = c & 7;
        int idx = (((ntg * 4 + ks) * 32) + qr * 4 + (cc & 3)) * 4 + (cc >> 2);
        g_Pf[idx]     = hi;
        g_Pf[idx + 2] = lo;
    }
}

// ===========================================================================
// FUSED k-projection + v-transpose + context GEMM.
// grid (BH, 16), 256 thr; block covers 256 n-rows in 16 chunks of 16.
// v^T staged as B-fragment tiles VT[nt(9)][lane][4] -> 1 LDS.128 per nt.
// ===========================================================================
__global__ void __launch_bounds__(256, 2)
k_fused_kctx(const float* __restrict__ kx, const float* __restrict__ vx)
{
    __shared__ uint32_t xhs[16 * 36], xls[16 * 36];
    __shared__ uint16_t Eth[256 * 24], Etl[256 * 24];   // [j][n halves], u32-stride 12
    __shared__ float vsm[16 * 68];                      // v chunk [n][e]
    __shared__ __align__(16) uint32_t VT[9 * 32 * 4];   // v^T B-fragment tiles
    __shared__ float diag[16];
    __shared__ float wmax[8];

    const int bh = blockIdx.x, s = blockIdx.y;
    const int tid = threadIdx.x, lane = tid & 31, wid = tid >> 5;
    const int qr = lane >> 2, qc = lane & 3;
    const size_t nbase = (size_t)bh * N4 + (size_t)s * 256;

    const uint4* Pf4 = (const uint4*)g_Pf;
    const uint4* VT4 = (const uint4*)VT;

    // fixed B tile nt=8: e=64 -> ones, 65..71 -> zeros
    if (tid < 64) {
        int e = 64 + (tid >> 3), w = tid & 7;
        int base = (8 * 32 + ((e & 7) * 4 + (w & 3))) * 4 + (w >> 2);
        VT[base]     = (e == 64) ? 0x3F803F80u : 0u;
        VT[base + 2] = 0u;
    }

    float c[2][9][4];
#pragma unroll
    for (int mt = 0; mt < 2; mt++)
#pragma unroll
        for (int nt = 0; nt < 9; nt++)
#pragma unroll
            for (int u = 0; u < 4; u++) c[mt][nt][u] = 0.f;
    float bmax = __int_as_float(0xff800000);
    float vacc = 0.f;

#pragma unroll 1
    for (int ch = 0; ch < 16; ch++) {
        __syncthreads();
        const float* xb = kx + (nbase + (size_t)ch * 16) * D;
        const float* vb = vx + (nbase + (size_t)ch * 16) * D;
#pragma unroll
        for (int it = 0; it < 2; it++) {
            int i = tid + it * 256;
            int r = i >> 5, cc = i & 31;
            float2 f = *(const float2*)(xb + r * 64 + 2 * cc);
            uint32_t hi, lo;
            split2(f.x, f.y, hi, lo);
            xhs[r * 36 + cc] = hi;
            xls[r * 36 + cc] = lo;
        }
        {
            int r = tid >> 4, c4 = tid & 15;
            *(float4*)(vsm + r * 68 + c4 * 4) = ((const float4*)(vb + r * 64))[c4];
        }
        {
            int r = tid >> 4, sub = tid & 15;
            float4 f = ((const float4*)(xb + r * 64))[sub];
            float sl = fmaf(f.x, f.x, fmaf(f.y, f.y, fmaf(f.z, f.z, f.w * f.w)));
#pragma unroll
            for (int o = 1; o < 16; o <<= 1)
                sl += __shfl_xor_sync(0xffffffffu, sl, o);
            if (sub == 0) diag[r] = sl * DIAG_C;
        }
        __syncthreads();

        if (tid < 64) {
#pragma unroll
            for (int n = 0; n < 16; n++) vacc += vsm[n * 68 + tid];
        }
        // transpose + split v -> fragment tiles (e<64)
#pragma unroll
        for (int it = 0; it < 2; it++) {
            int i = tid + it * 256;
            int e = i >> 3, w = i & 7;
            uint32_t hi, lo;
            split2(vsm[(2 * w) * 68 + e], vsm[(2 * w + 1) * 68 + e], hi, lo);
            int base = ((e >> 3) * 32 + (e & 7) * 4 + (w & 3)) * 4 + (w >> 2);
            VT[base]     = hi;
            VT[base + 2] = lo;
        }

        float cp[4][4];
#pragma unroll
        for (int nt = 0; nt < 4; nt++)
#pragma unroll
            for (int u = 0; u < 4; u++) cp[nt][u] = 0.f;
#pragma unroll
        for (int ks = 0; ks < 4; ks++) {
            const int kx8 = ks * 8;
            uint32_t ahi[4], alo[4];
            ahi[0] = xhs[qr * 36 + kx8 + qc];
            ahi[1] = xhs[(qr + 8) * 36 + kx8 + qc];
            ahi[2] = xhs[qr * 36 + kx8 + 4 + qc];
            ahi[3] = xhs[(qr + 8) * 36 + kx8 + 4 + qc];
            alo[0] = xls[qr * 36 + kx8 + qc];
            alo[1] = xls[(qr + 8) * 36 + kx8 + qc];
            alo[2] = xls[qr * 36 + kx8 + 4 + qc];
            alo[3] = xls[(qr + 8) * 36 + kx8 + 4 + qc];
#pragma unroll
            for (int nt = 0; nt < 4; nt++) {
                uint4 bf = Pf4[((wid * 4 + nt) * 4 + ks) * 32 + lane];
                uint32_t bhi[2] = {bf.x, bf.y};
                uint32_t blo[2] = {bf.z, bf.w};
                mma16(cp[nt], ahi, bhi);
                mma16(cp[nt], alo, bhi);
                mma16(cp[nt], ahi, blo);
            }
        }
        {
            float d0 = diag[qr], d1 = diag[qr + 8];
#pragma unroll
            for (int nt = 0; nt < 4; nt++) {
                bmax = fmaxf(bmax, fmaxf(fmaxf(cp[nt][0], cp[nt][1]),
                                         fmaxf(cp[nt][2], cp[nt][3])));
                int j0 = wid * 32 + nt * 8 + qc * 2;
                float v00 = fexp(fmaf(cp[nt][0], DATA_NORM, -d0));
                float v01 = fexp(fmaf(cp[nt][1], DATA_NORM, -d0));
                float v10 = fexp(fmaf(cp[nt][2], DATA_NORM, -d1));
                float v11 = fexp(fmaf(cp[nt][3], DATA_NORM, -d1));
                __nv_bfloat16 h; float hf;
                h = __float2bfloat16(v00); hf = __bfloat162float(h);
                Eth[j0 * 24 + qr] = *(uint16_t*)&h;
                { __nv_bfloat16 l = __float2bfloat16(v00 - hf); Etl[j0 * 24 + qr] = *(uint16_t*)&l; }
                h = __float2bfloat16(v01); hf = __bfloat162float(h);
                Eth[(j0 + 1) * 24 + qr] = *(uint16_t*)&h;
                { __nv_bfloat16 l = __float2bfloat16(v01 - hf); Etl[(j0 + 1) * 24 + qr] = *(uint16_t*)&l; }
                h = __float2bfloat16(v10); hf = __bfloat162float(h);
                Eth[j0 * 24 + qr + 8] = *(uint16_t*)&h;
                { __nv_bfloat16 l = __float2bfloat16(v10 - hf); Etl[j0 * 24 + qr + 8] = *(uint16_t*)&l; }
                h = __float2bfloat16(v11); hf = __bfloat162float(h);
                Eth[(j0 + 1) * 24 + qr + 8] = *(uint16_t*)&h;
                { __nv_bfloat16 l = __float2bfloat16(v11 - hf); Etl[(j0 + 1) * 24 + qr + 8] = *(uint16_t*)&l; }
            }
        }
        __syncthreads();

        const uint32_t* Eh32 = (const uint32_t*)Eth;
        const uint32_t* El32 = (const uint32_t*)Etl;
        uint32_t ahc[2][4], alc[2][4];
#pragma unroll
        for (int mt = 0; mt < 2; mt++) {
            int j = wid * 32 + mt * 16 + qr;
            ahc[mt][0] = Eh32[j * 12 + qc];
            ahc[mt][1] = Eh32[(j + 8) * 12 + qc];
            ahc[mt][2] = Eh32[j * 12 + 4 + qc];
            ahc[mt][3] = Eh32[(j + 8) * 12 + 4 + qc];
            alc[mt][0] = El32[j * 12 + qc];
            alc[mt][1] = El32[(j + 8) * 12 + qc];
            alc[mt][2] = El32[j * 12 + 4 + qc];
            alc[mt][3] = El32[(j + 8) * 12 + 4 + qc];
        }
#pragma unroll
        for (int nt = 0; nt < 9; nt++) {
            uint4 bf = VT4[nt * 32 + lane];
            uint32_t bhi[2] = {bf.x, bf.y};
            uint32_t blo[2] = {bf.z, bf.w};
#pragma unroll
            for (int mt = 0; mt < 2; mt++) {
                mma16(c[mt][nt], ahc[mt], bhi);
                mma16(c[mt][nt], alc[mt], bhi);
                mma16(c[mt][nt], ahc[mt], blo);
            }
        }
    }

#pragma unroll
    for (int o = 16; o > 0; o >>= 1)
        bmax = fmaxf(bmax, __shfl_xor_sync(0xffffffffu, bmax, o));
    if (lane == 0) wmax[wid] = bmax;
    __syncthreads();
    if (tid == 0) {
        float m = wmax[0];
#pragma unroll
        for (int w = 1; w < 8; w++) m = fmaxf(m, wmax[w]);
        atomicMax(&g_kmax_u, fenc(m * DATA_NORM));
    }
    if (tid < 64) g_vsump[(bh * SPLIT + s) * 64 + tid] = vacc;

    const size_t ob = (size_t)(bh * SPLIT + s) * 256;
#pragma unroll
    for (int mt = 0; mt < 2; mt++) {
        int j = wid * 32 + mt * 16 + qr;
#pragma unroll
        for (int nt = 0; nt < 9; nt++) {
            int e = nt * 8 + qc * 2;
            *(float2*)&g_ctxp[(ob + j) * 72 + e]     = make_float2(c[mt][nt][0], c[mt][nt][1]);
            *(float2*)&g_ctxp[(ob + j + 8) * 72 + e] = make_float2(c[mt][nt][2], c[mt][nt][3]);
        }
    }
}

// ===========================================================================
// Reduce + affine + split -> g_boutf (B-fragment order).  grid (BH, 8).
// ===========================================================================
__global__ void __launch_bounds__(256) k_red()
{
    __shared__ float sm[32 * 73];
    __shared__ float vsum[64];
    const int bh = blockIdx.x, g = blockIdx.y, tid = threadIdx.x;

    if (tid < 64) {
        float s = 0.f;
#pragma unroll
        for (int cg = 0; cg < SPLIT; cg++) s += g_vsump[(bh * SPLIT + cg) * 64 + tid];
        vsum[tid] = s;
    }
    {
        const int jl = tid >> 3, eg = tid & 7;
        float acc[9];
#pragma unroll
        for (int u = 0; u < 9; u++) acc[u] = 0.f;
        for (int s = 0; s < SPLIT; s++) {
            const float* p = &g_ctxp[((size_t)(bh * SPLIT + s) * 256 + g * 32 + jl) * 72 + eg * 9];
#pragma unroll
            for (int u = 0; u < 9; u++) acc[u] += p[u];
        }
#pragma unroll
        for (int u = 0; u < 9; u++) sm[jl * 73 + eg * 9 + u] = acc[u];
    }
    __syncthreads();

    const float m = fdec(g_kmax_u);
    const float em = RATIO * expf(-m);
    const float epsn = RATIO * KEPS;
    for (int i = tid; i < 72 * 16; i += 256) {
        int e = i >> 4, jwl = i & 15;
        float v0 = sm[(2 * jwl) * 73 + e], v1 = sm[(2 * jwl + 1) * 73 + e];
        float a0, a1;
        if (e < 64)       { a0 = fmaf(em, v0, epsn * vsum[e]); a1 = fmaf(em, v1, epsn * vsum[e]); }
        else if (e == 64) { a0 = fmaf(em, v0, epsn * (float)N4); a1 = fmaf(em, v1, epsn * (float)N4); }
        else              { a0 = 0.f; a1 = 0.f; }
        uint32_t hi, lo;
        split2(a0, a1, hi, lo);
        int w = g * 16 + jwl;                 // word index 0..127
        int kc = w >> 3, cc = w & 7;
        size_t idx = ((((size_t)bh * 9 + (e >> 3)) * 16 + kc) * 32 + (e & 7) * 4 + (cc & 3)) * 4 + (cc >> 2);
        g_boutf[idx]     = hi;
        g_boutf[idx + 2] = lo;
    }
}

// ===========================================================================
// FUSED q-projection + output GEMM (R13 semantics, fragment-tiled operands).
// 1024 blocks x 128 rows (8 chunks of 16).
// Q fragments in QTh/QTl[kc][lane][4] (LDS.128 pair); bout as B-frag slab.
// ===========================================================================
constexpr size_t SMEM_QOUT =
    (size_t)(18432 + 2 * 2048 + 2 * 16 * 36) * sizeof(uint32_t);

__global__ void __launch_bounds__(256, 2)
k_fused_qout(const float* __restrict__ qx, float* __restrict__ out)
{
    extern __shared__ uint32_t smu[];
    uint32_t* Bf  = smu;                        // [9 nt][16 kc][32 lane][4]
    uint32_t* QTh = Bf + 18432;                 // [16 kc][32 lane][4]
    uint32_t* QTl = QTh + 2048;
    uint32_t* xhs = QTl + 2048;                 // [16][36]
    uint32_t* xls = xhs + 16 * 36;
    __shared__ float diag[16];
    __shared__ float rmaxs[16][8];
    __shared__ float denp[8][16];

    const size_t row0 = (size_t)blockIdx.x * 128;
    const int bh = (int)(row0 >> 12);
    const int tid = threadIdx.x, lane = tid & 31, wid = tid >> 5;
    const int qr = lane >> 2, qc = lane & 3;

    const uint4* Pf4 = (const uint4*)g_Pf;
    const uint4* Bf4 = (const uint4*)Bf;

    // stage bout fragment slab (straight uint4 copy)
    {
        const uint4* src = (const uint4*)g_boutf + (size_t)bh * 4608;
        uint4* dst = (uint4*)Bf;
        for (int i = tid; i < 4608; i += 256) dst[i] = src[i];
    }

#pragma unroll 1
    for (int ch = 0; ch < 8; ch++) {
        __syncthreads();   // prev chunk consumed QT/denp; Bf ready (ch 0)
        const float* xb = qx + (row0 + (size_t)ch * 16) * D;
#pragma unroll
        for (int it = 0; it < 2; it++) {
            int i = tid + it * 256;
            int r = i >> 5, cc = i & 31;
            float2 f = *(const float2*)(xb + r * 64 + 2 * cc);
            uint32_t hi, lo;
            split2(f.x, f.y, hi, lo);
            xhs[r * 36 + cc] = hi;
            xls[r * 36 + cc] = lo;
        }
        {
            int r = tid >> 4, sub = tid & 15;
            float4 f = ((const float4*)(xb + r * 64))[sub];
            float sl = fmaf(f.x, f.x, fmaf(f.y, f.y, fmaf(f.z, f.z, f.w * f.w)));
#pragma unroll
            for (int o = 1; o < 16; o <<= 1)
                sl += __shfl_xor_sync(0xffffffffu, sl, o);
            if (sub == 0) diag[r] = sl * DIAG_C;
        }
        __syncthreads();

        // proj: warp wid covers j span wid*32
        float cp[4][4];
#pragma unroll
        for (int nt = 0; nt < 4; nt++)
#pragma unroll
            for (int u = 0; u < 4; u++) cp[nt][u] = 0.f;
#pragma unroll
        for (int ks = 0; ks < 4; ks++) {
            const int kx8 = ks * 8;
            uint32_t ahi[4], alo[4];
            ahi[0] = xhs[qr * 36 + kx8 + qc];
            ahi[1] = xhs[(qr + 8) * 36 + kx8 + qc];
            ahi[2] = xhs[qr * 36 + kx8 + 4 + qc];
            ahi[3] = xhs[(qr + 8) * 36 + kx8 + 4 + qc];
            alo[0] = xls[qr * 36 + kx8 + qc];
            alo[1] = xls[(qr + 8) * 36 + kx8 + qc];
            alo[2] = xls[qr * 36 + kx8 + 4 + qc];
            alo[3] = xls[(qr + 8) * 36 + kx8 + 4 + qc];
#pragma unroll
            for (int nt = 0; nt < 4; nt++) {
                uint4 bf = Pf4[((wid * 4 + nt) * 4 + ks) * 32 + lane];
                uint32_t bhi[2] = {bf.x, bf.y};
                uint32_t blo[2] = {bf.z, bf.w};
                mma16(cp[nt], ahi, bhi);
                mma16(cp[nt], alo, bhi);
                mma16(cp[nt], ahi, blo);
            }
        }

        // cross-warp rowmax
        {
            float r0 = __int_as_float(0xff800000), r1 = r0;
#pragma unroll
            for (int nt = 0; nt < 4; nt++) {
                r0 = fmaxf(r0, fmaxf(cp[nt][0], cp[nt][1]));
                r1 = fmaxf(r1, fmaxf(cp[nt][2], cp[nt][3]));
            }
            r0 = fmaxf(r0, __shfl_xor_sync(0xffffffffu, r0, 1));
            r0 = fmaxf(r0, __shfl_xor_sync(0xffffffffu, r0, 2));
            r1 = fmaxf(r1, __shfl_xor_sync(0xffffffffu, r1, 1));
            r1 = fmaxf(r1, __shfl_xor_sync(0xffffffffu, r1, 2));
            if (qc == 0) { rmaxs[qr][wid] = r0; rmaxs[qr + 8][wid] = r1; }
        }
        __syncthreads();

        // qp = RATIO*(fexp(dd*DN - diag - rowmax)+eps) -> A-fragment tiles
        {
            float m0 = rmaxs[qr][0], m1 = rmaxs[qr + 8][0];
#pragma unroll
            for (int w = 1; w < 8; w++) {
                m0 = fmaxf(m0, rmaxs[qr][w]);
                m1 = fmaxf(m1, rmaxs[qr + 8][w]);
            }
            float sub0 = diag[qr] + m0 * DATA_NORM;
            float sub1 = diag[qr + 8] + m1 * DATA_NORM;
#pragma unroll
            for (int nt = 0; nt < 4; nt++) {
                int w = wid * 16 + nt * 4 + qc;       // word index = j0/2
                float v00 = RATIO * (fexp(fmaf(cp[nt][0], DATA_NORM, -sub0)) + KEPS);
                float v01 = RATIO * (fexp(fmaf(cp[nt][1], DATA_NORM, -sub0)) + KEPS);
                float v10 = RATIO * (fexp(fmaf(cp[nt][2], DATA_NORM, -sub1)) + KEPS);
                float v11 = RATIO * (fexp(fmaf(cp[nt][3], DATA_NORM, -sub1)) + KEPS);
                uint32_t h0, l0, h1, l1;
                split2(v00, v01, h0, l0);             // row qr
                split2(v10, v11, h1, l1);             // row qr+8
                int kc = w >> 3;
                int base = (kc * 32 + lane) * 4 + ((w & 4) ? 2 : 0);
                *(uint2*)&QTh[base] = make_uint2(h0, h1);
                *(uint2*)&QTl[base] = make_uint2(l0, l1);
            }
        }
        __syncthreads();

        // out GEMM: warp wid owns e tile nt=wid; den (nt=8) K-split kc {2w,2w+1}
        float co[4] = {0.f, 0.f, 0.f, 0.f};
        float cd[4] = {0.f, 0.f, 0.f, 0.f};
#pragma unroll
        for (int kc = 0; kc < 16; kc++) {
            uint4 ahiv = *(const uint4*)&QTh[(kc * 32 + lane) * 4];
            uint4 alov = *(const uint4*)&QTl[(kc * 32 + lane) * 4];
            {
                uint4 bf = Bf4[(wid * 16 + kc) * 32 + lane];
                uint32_t bhi[2] = {bf.x, bf.y};
                uint32_t blo[2] = {bf.z, bf.w};
                mma16(co, (const uint32_t*)&ahiv, bhi);
                mma16(co, (const uint32_t*)&alov, bhi);
                mma16(co, (const uint32_t*)&ahiv, blo);
            }
            if ((kc >> 1) == wid) {
                uint4 bf = Bf4[(8 * 16 + kc) * 32 + lane];
                uint32_t bhi[2] = {bf.x, bf.y};
                uint32_t blo[2] = {bf.z, bf.w};
                mma16(cd, (const uint32_t*)&ahiv, bhi);
                mme: ;
                mma16(cd, (const uint32_t*)&alov, bhi);
                mma16(cd, (const uint32_t*)&ahiv, blo);
            }
        }
        if (qc == 0) {
            denp[wid][qr]     = cd[0];
            denp[wid][qr + 8] = cd[2];
        }
        __syncthreads();
        {
            float d0 = denp[0][qr],     d1 = denp[0][qr + 8];
#pragma unroll
            for (int w = 1; w < 8; w++) { d0 += denp[w][qr]; d1 += denp[w][qr + 8]; }
            float di0 = 1.f / d0, di1 = 1.f / d1;
            size_t rb = row0 + (size_t)ch * 16;
            int e = wid * 8 + qc * 2;
            *(float2*)&out[(rb + qr) * D + e]     = make_float2(co[0] * di0, co[1] * di0);
            *(float2*)&out[(rb + qr + 8) * D + e] = make_float2(co[2] * di1, co[3] * di1);
        }
    }
}

} // namespace fa

extern "C" void kernel_launch(void* const* d_in, const int* in_sizes, int n_in,
                              void* d_out, int out_size)
{
    using namespace fa;
    (void)in_sizes; (void)n_in; (void)out_size;

    const float* q = (const float*)d_in[0];
    const float* k = (const float*)d_in[1];
    const float* v = (const float*)d_in[2];
    const float* P = (const float*)d_in[3];
    float* out = (float*)d_out;

    cudaFuncSetAttribute(k_fused_qout, cudaFuncAttributeMaxDynamicSharedMemorySize, (int)SMEM_QOUT);

    k_prep_P<<<1, 256>>>(P);
    k_fused_kctx<<<dim3(BH, SPLIT), 256>>>(k, v);              // proj-k + v^T + ctx
    k_red<<<dim3(BH, 8), 256>>>();                             // affine + boutf
    k_fused_qout<<<(int)(NT / 128), 256, SMEM_QOUT>>>(q, out); // proj-q + out
}

// round 17
// speedup vs baseline: 1.0481x; 1.0481x over previous
#include <cuda_runtime.h>
#include <cuda_bf16.h>
#include <math.h>
#include <stdint.h>

namespace fa {

constexpr int N4 = 4096, D = 64, J = 256, BH = 32, SPLIT = 16;
constexpr size_t NT = (size_t)BH * N4;          // 131072 rows

constexpr float DATA_NORM = 0.35355339059327373f;
constexpr float RATIO     = 0.0625f;
constexpr float DIAG_C    = 0.0625f;
constexpr float KEPS      = 1e-4f;

// ---- scratch ----
// P in mma-B fragment order: [jtile(32)][ks(4)][lane(32)][4: hi0,hi1,lo0,lo1]
__device__ __align__(16) uint32_t g_Pf[32 * 4 * 32 * 4];
__device__ float    g_vsump[BH * SPLIT * 64];
__device__ float    g_ctxp[(size_t)BH * SPLIT * 256 * 72];
__device__ __align__(16) uint32_t g_bout_h[BH * 72 * 128];
__device__ __align__(16) uint32_t g_bout_l[BH * 72 * 128];
__device__ unsigned g_kmax_u;

__device__ __forceinline__ unsigned fenc(float f) {
    unsigned u = __float_as_uint(f);
    return (u & 0x80000000u) ? ~u : (u | 0x80000000u);
}
__device__ __forceinline__ float fdec(unsigned u) {
    unsigned b = (u & 0x80000000u) ? (u & 0x7fffffffu) : ~u;
    return __uint_as_float(b);
}
__device__ __forceinline__ uint32_t bpack(float a, float b) {
    uint32_t r;
    asm("cvt.rn.bf16x2.f32 %0, %1, %2;" : "=r"(r) : "f"(b), "f"(a));
    return r;
}
__device__ __forceinline__ void split2(float a, float b, uint32_t& hi, uint32_t& lo) {
    hi = bpack(a, b);
    float ha = __uint_as_float(hi << 16);
    float hb = __uint_as_float(hi & 0xffff0000u);
    lo = bpack(a - ha, b - hb);
}
// fp32 exp via FMA-pipe poly (rel err ~1.7e-7)
__device__ __forceinline__ float fexp(float x) {
    float t = x * 1.4426950408889634f;
    float r = rintf(t);
    float f = t - r;
    float p = 1.53989857e-4f;
    p = fmaf(p, f, 1.33335581e-3f);
    p = fmaf(p, f, 9.61812910e-3f);
    p = fmaf(p, f, 5.55041087e-2f);
    p = fmaf(p, f, 2.40226507e-1f);
    p = fmaf(p, f, 6.93147181e-1f);
    p = fmaf(p, f, 1.0f);
    int ei = (int)r;
    ei = ei < -126 ? -126 : (ei > 127 ? 127 : ei);
    return p * __int_as_float((ei + 127) << 23);
}
__device__ __forceinline__ void mma16(float* c, const uint32_t* a, const uint32_t* b) {
    asm volatile(
        "mma.sync.aligned.m16n8k16.row.col.f32.bf16.bf16.f32 "
        "{%0,%1,%2,%3}, {%4,%5,%6,%7}, {%8,%9}, {%0,%1,%2,%3};"
        : "+f"(c[0]), "+f"(c[1]), "+f"(c[2]), "+f"(c[3])
        : "r"(a[0]), "r"(a[1]), "r"(a[2]), "r"(a[3]), "r"(b[0]), "r"(b[1]));
}

// ===========================================================================
// Prep P -> g_Pf (B-fragment order) + init max.  <<<1,256>>>, thread = row j.
// ===========================================================================
__global__ void k_prep_P(const float* __restrict__ P)
{
    const int j = threadIdx.x;
    if (j == 0) g_kmax_u = 0x007FFFFFu;
    const int ntg = j >> 3, qr = j & 7;
#pragma unroll
    for (int c = 0; c < 32; c++) {
        uint32_t hi, lo;
        split2(P[j * 64 + 2 * c], P[j * 64 + 2 * c + 1], hi, lo);
        int ks = c >> 3, cc = c & 7;
        int idx = (((ntg * 4 + ks) * 32) + qr * 4 + (cc & 3)) * 4 + (cc >> 2);
        g_Pf[idx]     = hi;
        g_Pf[idx + 2] = lo;
    }
}

// ===========================================================================
// FUSED k-projection + v-transpose + context GEMM (R16 version: VT fragment
// tiles, 1 LDS.128 per B fetch).  grid (BH, 16), 256 thr; 16 chunks of 16.
// ===========================================================================
__global__ void __launch_bounds__(256, 2)
k_fused_kctx(const float* __restrict__ kx, const float* __restrict__ vx)
{
    __shared__ uint32_t xhs[16 * 36], xls[16 * 36];
    __shared__ uint16_t Eth[256 * 24], Etl[256 * 24];   // [j][n halves], u32-stride 12
    __shared__ float vsm[16 * 68];                      // v chunk [n][e]
    __shared__ __align__(16) uint32_t VT[9 * 32 * 4];   // v^T B-fragment tiles
    __shared__ float diag[16];
    __shared__ float wmax[8];

    const int bh = blockIdx.x, s = blockIdx.y;
    const int tid = threadIdx.x, lane = tid & 31, wid = tid >> 5;
    const int qr = lane >> 2, qc = lane & 3;
    const size_t nbase = (size_t)bh * N4 + (size_t)s * 256;

    const uint4* Pf4 = (const uint4*)g_Pf;
    const uint4* VT4 = (const uint4*)VT;

    // fixed B tile nt=8: e=64 -> ones, 65..71 -> zeros
    if (tid < 64) {
        int e = 64 + (tid >> 3), w = tid & 7;
        int base = (8 * 32 + ((e & 7) * 4 + (w & 3))) * 4 + (w >> 2);
        VT[base]     = (e == 64) ? 0x3F803F80u : 0u;
        VT[base + 2] = 0u;
    }

    float c[2][9][4];
#pragma unroll
    for (int mt = 0; mt < 2; mt++)
#pragma unroll
        for (int nt = 0; nt < 9; nt++)
#pragma unroll
            for (int u = 0; u < 4; u++) c[mt][nt][u] = 0.f;
    float bmax = __int_as_float(0xff800000);
    float vacc = 0.f;

#pragma unroll 1
    for (int ch = 0; ch < 16; ch++) {
        __syncthreads();
        const float* xb = kx + (nbase + (size_t)ch * 16) * D;
        const float* vb = vx + (nbase + (size_t)ch * 16) * D;
#pragma unroll
        for (int it = 0; it < 2; it++) {
            int i = tid + it * 256;
            int r = i >> 5, cc = i & 31;
            float2 f = *(const float2*)(xb + r * 64 + 2 * cc);
            uint32_t hi, lo;
            split2(f.x, f.y, hi, lo);
            xhs[r * 36 + cc] = hi;
            xls[r * 36 + cc] = lo;
        }
        {
            int r = tid >> 4, c4 = tid & 15;
            *(float4*)(vsm + r * 68 + c4 * 4) = ((const float4*)(vb + r * 64))[c4];
        }
        {
            int r = tid >> 4, sub = tid & 15;
            float4 f = ((const float4*)(xb + r * 64))[sub];
            float sl = fmaf(f.x, f.x, fmaf(f.y, f.y, fmaf(f.z, f.z, f.w * f.w)));
#pragma unroll
            for (int o = 1; o < 16; o <<= 1)
                sl += __shfl_xor_sync(0xffffffffu, sl, o);
            if (sub == 0) diag[r] = sl * DIAG_C;
        }
        __syncthreads();

        if (tid < 64) {
#pragma unroll
            for (int n = 0; n < 16; n++) vacc += vsm[n * 68 + tid];
        }
        // transpose + split v -> fragment tiles (e<64)
#pragma unroll
        for (int it = 0; it < 2; it++) {
            int i = tid + it * 256;
            int e = i >> 3, w = i & 7;
            uint32_t hi, lo;
            split2(vsm[(2 * w) * 68 + e], vsm[(2 * w + 1) * 68 + e], hi, lo);
            int base = ((e >> 3) * 32 + (e & 7) * 4 + (w & 3)) * 4 + (w >> 2);
            VT[base]     = hi;
            VT[base + 2] = lo;
        }

        float cp[4][4];
#pragma unroll
        for (int nt = 0; nt < 4; nt++)
#pragma unroll
            for (int u = 0; u < 4; u++) cp[nt][u] = 0.f;
#pragma unroll
        for (int ks = 0; ks < 4; ks++) {
            const int kx8 = ks * 8;
            uint32_t ahi[4], alo[4];
            ahi[0] = xhs[qr * 36 + kx8 + qc];
            ahi[1] = xhs[(qr + 8) * 36 + kx8 + qc];
            ahi[2] = xhs[qr * 36 + kx8 + 4 + qc];
            ahi[3] = xhs[(qr + 8) * 36 + kx8 + 4 + qc];
            alo[0] = xls[qr * 36 + kx8 + qc];
            alo[1] = xls[(qr + 8) * 36 + kx8 + qc];
            alo[2] = xls[qr * 36 + kx8 + 4 + qc];
            alo[3] = xls[(qr + 8) * 36 + kx8 + 4 + qc];
#pragma unroll
            for (int nt = 0; nt < 4; nt++) {
                uint4 bf = Pf4[((wid * 4 + nt) * 4 + ks) * 32 + lane];
                uint32_t bhi[2] = {bf.x, bf.y};
                uint32_t blo[2] = {bf.z, bf.w};
                mma16(cp[nt], ahi, bhi);
                mma16(cp[nt], alo, bhi);
                mma16(cp[nt], ahi, blo);
            }
        }
        {
            float d0 = diag[qr], d1 = diag[qr + 8];
#pragma unroll
            for (int nt = 0; nt < 4; nt++) {
                bmax = fmaxf(bmax, fmaxf(fmaxf(cp[nt][0], cp[nt][1]),
                                         fmaxf(cp[nt][2], cp[nt][3])));
                int j0 = wid * 32 + nt * 8 + qc * 2;
                float v00 = fexp(fmaf(cp[nt][0], DATA_NORM, -d0));
                float v01 = fexp(fmaf(cp[nt][1], DATA_NORM, -d0));
                float v10 = fexp(fmaf(cp[nt][2], DATA_NORM, -d1));
                float v11 = fexp(fmaf(cp[nt][3], DATA_NORM, -d1));
                __nv_bfloat16 h; float hf;
                h = __float2bfloat16(v00); hf = __bfloat162float(h);
                Eth[j0 * 24 + qr] = *(uint16_t*)&h;
                { __nv_bfloat16 l = __float2bfloat16(v00 - hf); Etl[j0 * 24 + qr] = *(uint16_t*)&l; }
                h = __float2bfloat16(v01); hf = __bfloat162float(h);
                Eth[(j0 + 1) * 24 + qr] = *(uint16_t*)&h;
                { __nv_bfloat16 l = __float2bfloat16(v01 - hf); Etl[(j0 + 1) * 24 + qr] = *(uint16_t*)&l; }
                h = __float2bfloat16(v10); hf = __bfloat162float(h);
                Eth[j0 * 24 + qr + 8] = *(uint16_t*)&h;
                { __nv_bfloat16 l = __float2bfloat16(v10 - hf); Etl[j0 * 24 + qr + 8] = *(uint16_t*)&l; }
                h = __float2bfloat16(v11); hf = __bfloat162float(h);
                Eth[(j0 + 1) * 24 + qr + 8] = *(uint16_t*)&h;
                { __nv_bfloat16 l = __float2bfloat16(v11 - hf); Etl[(j0 + 1) * 24 + qr + 8] = *(uint16_t*)&l; }
            }
        }
        __syncthreads();

        const uint32_t* Eh32 = (const uint32_t*)Eth;
        const uint32_t* El32 = (const uint32_t*)Etl;
        uint32_t ahc[2][4], alc[2][4];
#pragma unroll
        for (int mt = 0; mt < 2; mt++) {
            int j = wid * 32 + mt * 16 + qr;
            ahc[mt][0] = Eh32[j * 12 + qc];
            ahc[mt][1] = Eh32[(j + 8) * 12 + qc];
            ahc[mt][2] = Eh32[j * 12 + 4 + qc];
            ahc[mt][3] = Eh32[(j + 8) * 12 + 4 + qc];
            alc[mt][0] = El32[j * 12 + qc];
            alc[mt][1] = El32[(j + 8) * 12 + qc];
            alc[mt][2] = El32[j * 12 + 4 + qc];
            alc[mt][3] = El32[(j + 8) * 12 + 4 + qc];
        }
#pragma unroll
        for (int nt = 0; nt < 9; nt++) {
            uint4 bf = VT4[nt * 32 + lane];
            uint32_t bhi[2] = {bf.x, bf.y};
            uint32_t blo[2] = {bf.z, bf.w};
#pragma unroll
            for (int mt = 0; mt < 2; mt++) {
                mma16(c[mt][nt], ahc[mt], bhi);
                mma16(c[mt][nt], alc[mt], bhi);
                mma16(c[mt][nt], ahc[mt], blo);
            }
        }
    }

#pragma unroll
    for (int o = 16; o > 0; o >>= 1)
        bmax = fmaxf(bmax, __shfl_xor_sync(0xffffffffu, bmax, o));
    if (lane == 0) wmax[wid] = bmax;
    __syncthreads();
    if (tid == 0) {
        float m = wmax[0];
#pragma unroll
        for (int w = 1; w < 8; w++) m = fmaxf(m, wmax[w]);
        atomicMax(&g_kmax_u, fenc(m * DATA_NORM));
    }
    if (tid < 64) g_vsump[(bh * SPLIT + s) * 64 + tid] = vacc;

    const size_t ob = (size_t)(bh * SPLIT + s) * 256;
#pragma unroll
    for (int mt = 0; mt < 2; mt++) {
        int j = wid * 32 + mt * 16 + qr;
#pragma unroll
        for (int nt = 0; nt < 9; nt++) {
            int e = nt * 8 + qc * 2;
            *(float2*)&g_ctxp[(ob + j) * 72 + e]     = make_float2(c[mt][nt][0], c[mt][nt][1]);
            *(float2*)&g_ctxp[(ob + j + 8) * 72 + e] = make_float2(c[mt][nt][2], c[mt][nt][3]);
        }
    }
}

// ===========================================================================
// Reduce + affine + split -> bout (R13 layout).  grid (BH, 8).
// ===========================================================================
__global__ void __launch_bounds__(256) k_red()
{
    __shared__ float sm[32 * 73];
    __shared__ float vsum[64];
    const int bh = blockIdx.x, g = blockIdx.y, tid = threadIdx.x;

    if (tid < 64) {
        float s = 0.f;
#pragma unroll
        for (int cg = 0; cg < SPLIT; cg++) s += g_vsump[(bh * SPLIT + cg) * 64 + tid];
        vsum[tid] = s;
    }
    {
        const int jl = tid >> 3, eg = tid & 7;
        float acc[9];
#pragma unroll
        for (int u = 0; u < 9; u++) acc[u] = 0.f;
        for (int s = 0; s < SPLIT; s++) {
            const float* p = &g_ctxp[((size_t)(bh * SPLIT + s) * 256 + g * 32 + jl) * 72 + eg * 9];
#pragma unroll
            for (int u = 0; u < 9; u++) acc[u] += p[u];
        }
#pragma unroll
        for (int u = 0; u < 9; u++) sm[jl * 73 + eg * 9 + u] = acc[u];
    }
    __syncthreads();

    const float m = fdec(g_kmax_u);
    const float em = RATIO * expf(-m);
    const float epsn = RATIO * KEPS;
    for (int i = tid; i < 72 * 16; i += 256) {
        int e = i >> 4, jwl = i & 15;
        float v0 = sm[(2 * jwl) * 73 + e], v1 = sm[(2 * jwl + 1) * 73 + e];
        float a0, a1;
        if (e < 64)       { a0 = fmaf(em, v0, epsn * vsum[e]); a1 = fmaf(em, v1, epsn * vsum[e]); }
        else if (e == 64) { a0 = fmaf(em, v0, epsn * (float)N4); a1 = fmaf(em, v1, epsn * (float)N4); }
        else              { a0 = 0.f; a1 = 0.f; }
        uint32_t hi, lo;
        split2(a0, a1, hi, lo);
        g_bout_h[(bh * 72 + e) * 128 + g * 16 + jwl] = hi;
        g_bout_l[(bh * 72 + e) * 128 + g * 16 + jwl] = lo;
    }
}

// ===========================================================================
// FUSED q-projection + output GEMM (exact R13 version).
// 1024 blocks x 128 rows (8 chunks of 16).
// ===========================================================================
constexpr int QW = 132;   // Qh/Ql row stride (u32)
constexpr size_t SMEM_QOUT =
    (size_t)(2 * 72 * 132 + 2 * 16 * QW + 2 * 16 * 36) * sizeof(uint32_t);

__global__ void __launch_bounds__(256, 2)
k_fused_qout(const float* __restrict__ qx, float* __restrict__ out)
{
    extern __shared__ uint32_t smu[];
    uint32_t* Bsh = smu;                        // [72][132]
    uint32_t* Bsl = Bsh + 72 * 132;
    uint32_t* Qh  = Bsl + 72 * 132;             // [16][QW]
    uint32_t* Ql  = Qh + 16 * QW;
    uint32_t* xhs = Ql + 16 * QW;               // [16][36]
    uint32_t* xls = xhs + 16 * 36;
    __shared__ float diag[16];
    __shared__ float rmaxs[16][8];
    __shared__ float denp[8][16];

    const size_t row0 = (size_t)blockIdx.x * 128;
    const int bh = (int)(row0 >> 12);
    const int tid = threadIdx.x, lane = tid & 31, wid = tid >> 5;
    const int qr = lane >> 2, qc = lane & 3;

    const uint4* Pf4 = (const uint4*)g_Pf;

    for (int i = tid; i < 72 * 32; i += 256) {
        int e = i >> 5, w4 = i & 31;
        size_t src = (size_t)(bh * 72 + e) * 128;
        *(float4*)(Bsh + e * 132 + w4 * 4) = ((const float4*)(g_bout_h + src))[w4];
        *(float4*)(Bsl + e * 132 + w4 * 4) = ((const float4*)(g_bout_l + src))[w4];
    }

#pragma unroll 1
    for (int ch = 0; ch < 8; ch++) {
        __syncthreads();   // prev chunk consumed Qh/denp; bout slab ready (ch 0)
        const float* xb = qx + (row0 + (size_t)ch * 16) * D;
#pragma unroll
        for (int it = 0; it < 2; it++) {
            int i = tid + it * 256;
            int r = i >> 5, cc = i & 31;
            float2 f = *(const float2*)(xb + r * 64 + 2 * cc);
            uint32_t hi, lo;
            split2(f.x, f.y, hi, lo);
            xhs[r * 36 + cc] = hi;
            xls[r * 36 + cc] = lo;
        }
        {
            int r = tid >> 4, sub = tid & 15;
            float4 f = ((const float4*)(xb + r * 64))[sub];
            float sl = fmaf(f.x, f.x, fmaf(f.y, f.y, fmaf(f.z, f.z, f.w * f.w)));
#pragma unroll
            for (int o = 1; o < 16; o <<= 1)
                sl += __shfl_xor_sync(0xffffffffu, sl, o);
            if (sub == 0) diag[r] = sl * DIAG_C;
        }
        __syncthreads();

        float cp[4][4];
#pragma unroll
        for (int nt = 0; nt < 4; nt++)
#pragma unroll
            for (int u = 0; u < 4; u++) cp[nt][u] = 0.f;
#pragma unroll
        for (int ks = 0; ks < 4; ks++) {
            const int kx8 = ks * 8;
            uint32_t ahi[4], alo[4];
            ahi[0] = xhs[qr * 36 + kx8 + qc];
            ahi[1] = xhs[(qr + 8) * 36 + kx8 + qc];
            ahi[2] = xhs[qr * 36 + kx8 + 4 + qc];
            ahi[3] = xhs[(qr + 8) * 36 + kx8 + 4 + qc];
            alo[0] = xls[qr * 36 + kx8 + qc];
            alo[1] = xls[(qr + 8) * 36 + kx8 + qc];
            alo[2] = xls[qr * 36 + kx8 + 4 + qc];
            alo[3] = xls[(qr + 8) * 36 + kx8 + 4 + qc];
#pragma unroll
            for (int nt = 0; nt < 4; nt++) {
                uint4 bf = Pf4[((wid * 4 + nt) * 4 + ks) * 32 + lane];
                uint32_t bhi[2] = {bf.x, bf.y};
                uint32_t blo[2] = {bf.z, bf.w};
                mma16(cp[nt], ahi, bhi);
                mma16(cp[nt], alo, bhi);
                mma16(cp[nt], ahi, blo);
            }
        }

        {
            float r0 = __int_as_float(0xff800000), r1 = r0;
#pragma unroll
            for (int nt = 0; nt < 4; nt++) {
                r0 = fmaxf(r0, fmaxf(cp[nt][0], cp[nt][1]));
                r1 = fmaxf(r1, fmaxf(cp[nt][2], cp[nt][3]));
            }
            r0 = fmaxf(r0, __shfl_xor_sync(0xffffffffu, r0, 1));
            r0 = fmaxf(r0, __shfl_xor_sync(0xffffffffu, r0, 2));
            r1 = fmaxf(r1, __shfl_xor_sync(0xffffffffu, r1, 1));
            r1 = fmaxf(r1, __shfl_xor_sync(0xffffffffu, r1, 2));
            if (qc == 0) { rmaxs[qr][wid] = r0; rmaxs[qr + 8][wid] = r1; }
        }
        __syncthreads();

        {
            float m0 = rmaxs[qr][0], m1 = rmaxs[qr + 8][0];
#pragma unroll
            for (int w = 1; w < 8; w++) {
                m0 = fmaxf(m0, rmaxs[qr][w]);
                m1 = fmaxf(m1, rmaxs[qr + 8][w]);
            }
            float sub0 = diag[qr] + m0 * DATA_NORM;
            float sub1 = diag[qr + 8] + m1 * DATA_NORM;
#pragma unroll
            for (int nt = 0; nt < 4; nt++) {
                int w = wid * 16 + nt * 4 + qc;
                float v00 = RATIO * (fexp(fmaf(cp[nt][0], DATA_NORM, -sub0)) + KEPS);
                float v01 = RATIO * (fexp(fmaf(cp[nt][1], DATA_NORM, -sub0)) + KEPS);
                float v10 = RATIO * (fexp(fmaf(cp[nt][2], DATA_NORM, -sub1)) + KEPS);
                float v11 = RATIO * (fexp(fmaf(cp[nt][3], DATA_NORM, -sub1)) + KEPS);
                uint32_t hi, lo;
                split2(v00, v01, hi, lo);
                Qh[qr * QW + w] = hi;
                Ql[qr * QW + w] = lo;
                split2(v10, v11, hi, lo);
                Qh[(qr + 8) * QW + w] = hi;
                Ql[(qr + 8) * QW + w] = lo;
            }
        }
        __syncthreads();

        float co[4] = {0.f, 0.f, 0.f, 0.f};
        float cd[4] = {0.f, 0.f, 0.f, 0.f};
#pragma unroll
        for (int kc = 0; kc < 16; kc++) {
            const int k0 = kc * 8;
            uint32_t ahi[4], alo[4];
            ahi[0] = Qh[qr * QW + k0 + qc];
            ahi[1] = Qh[(qr + 8) * QW + k0 + qc];
            ahi[2] = Qh[qr * QW + k0 + 4 + qc];
            ahi[3] = Qh[(qr + 8) * QW + k0 + 4 + qc];
            alo[0] = Ql[qr * QW + k0 + qc];
            alo[1] = Ql[(qr + 8) * QW + k0 + qc];
            alo[2] = Ql[qr * QW + k0 + 4 + qc];
            alo[3] = Ql[(qr + 8) * QW + k0 + 4 + qc];
            {
                int e = wid * 8 + qr;
                uint32_t bhi[2], blo[2];
                bhi[0] = Bsh[e * 132 + k0 + qc];
                bhi[1] = Bsh[e * 132 + k0 + 4 + qc];
                blo[0] = Bsl[e * 132 + k0 + qc];
                blo[1] = Bsl[e * 132 + k0 + 4 + qc];
                mma16(co, ahi, bhi);
                mma16(co, alo, bhi);
                mma16(co, ahi, blo);
            }
            if ((kc >> 1) == wid) {
                int e = 64 + qr;
                uint32_t bhi[2], blo[2];
                bhi[0] = Bsh[e * 132 + k0 + qc];
                bhi[1] = Bsh[e * 132 + k0 + 4 + qc];
                blo[0] = Bsl[e * 132 + k0 + qc];
                blo[1] = Bsl[e * 132 + k0 + 4 + qc];
                mma16(cd, ahi, bhi);
                mma16(cd, alo, bhi);
                mma16(cd, ahi, blo);
            }
        }
        if (qc == 0) {
            denp[wid][qr]     = cd[0];
            denp[wid][qr + 8] = cd[2];
        }
        __syncthreads();
        {
            float d0 = denp[0][qr],     d1 = denp[0][qr + 8];
#pragma unroll
            for (int w = 1; w < 8; w++) { d0 += denp[w][qr]; d1 += denp[w][qr + 8]; }
            float di0 = 1.f / d0, di1 = 1.f / d1;
            size_t rb = row0 + (size_t)ch * 16;
            int e = wid * 8 + qc * 2;
            *(float2*)&out[(rb + qr) * D + e]     = make_float2(co[0] * di0, co[1] * di0);
            *(float2*)&out[(rb + qr + 8) * D + e] = make_float2(co[2] * di1, co[3] * di1);
        }
    }
}

} // namespace fa

extern "C" void kernel_launch(void* const* d_in, const int* in_sizes, int n_in,
                              void* d_out, int out_size)
{
    using namespace fa;
    (void)in_sizes; (void)n_in; (void)out_size;

    const float* q = (const float*)d_in[0];
    const float* k = (const float*)d_in[1];
    const float* v = (const float*)d_in[2];
    const float* P = (const float*)d_in[3];
    float* out = (float*)d_out;

    cudaFuncSetAttribute(k_fused_qout, cudaFuncAttributeMaxDynamicSharedMemorySize, (int)SMEM_QOUT);

    k_prep_P<<<1, 256>>>(P);
    k_fused_kctx<<<dim3(BH, SPLIT), 256>>>(k, v);              // proj-k + v^T + ctx (VT frags)
    k_red<<<dim3(BH, 8), 256>>>();                             // affine + bout
    k_fused_qout<<<(int)(NT / 128), 256, SMEM_QOUT>>>(q, out); // proj-q + out (R13)
}